// round 1
// baseline (speedup 1.0000x reference)
#include <cuda_runtime.h>
#include <cuda_bf16.h>
#include <cstdint>

// Problem constants (fixed shapes for this problem instance)
#define BATCH 2
#define SEQ   2048
#define DIM   1024
#define HEADS 16
#define DHEAD 64

// Scratch (device globals — no allocations allowed in kernel_launch)
__device__ float g_qkv[(size_t)BATCH * SEQ * 3 * DIM];   // [B, S, 3D]
__device__ float g_attn[(size_t)BATCH * SEQ * DIM];      // [B, S, D]

// ---------------------------------------------------------------------------
// SGEMM: C[m,n] = sum_k A[m,k] * B[n,k] + bias[n]
// A: [M,K] row-major, B: [N,K] row-major (i.e. computes A @ B^T + bias)
// BM=BN=128, BK=8, 256 threads, 8x8 per thread.
// Requires M%128==0, N%128==0, K%8==0 (true for all our shapes).
// ---------------------------------------------------------------------------
__global__ __launch_bounds__(256)
void sgemm_nt_bias(int M, int N, int K,
                   const float* __restrict__ A,
                   const float* __restrict__ B,
                   const float* __restrict__ bias,
                   float* __restrict__ C)
{
    constexpr int BM = 128, BN = 128, BK = 8, TM = 8, TN = 8;
    __shared__ float As[BK][BM];
    __shared__ float Bs[BK][BN];

    const int bx = blockIdx.x;   // N tile
    const int by = blockIdx.y;   // M tile
    const int tid = threadIdx.x;

    // load mapping: each thread loads one float4 from A and one from B
    const int lrow = tid >> 1;          // 0..127
    const int lcol = (tid & 1) * 4;     // 0 or 4

    // compute mapping
    const int tx = tid & 15;            // 0..15
    const int ty = tid >> 4;            // 0..15
    const int tm0 = ty * TM;
    const int tn0 = tx * TN;

    const float* Ab = A + (size_t)(by * BM) * K;
    const float* Bb = B + (size_t)(bx * BN) * K;

    float acc[TM][TN];
#pragma unroll
    for (int i = 0; i < TM; i++)
#pragma unroll
        for (int j = 0; j < TN; j++) acc[i][j] = 0.0f;

    for (int k0 = 0; k0 < K; k0 += BK) {
        float4 a4 = *(const float4*)(Ab + (size_t)lrow * K + k0 + lcol);
        float4 b4 = *(const float4*)(Bb + (size_t)lrow * K + k0 + lcol);
        As[lcol + 0][lrow] = a4.x;
        As[lcol + 1][lrow] = a4.y;
        As[lcol + 2][lrow] = a4.z;
        As[lcol + 3][lrow] = a4.w;
        Bs[lcol + 0][lrow] = b4.x;
        Bs[lcol + 1][lrow] = b4.y;
        Bs[lcol + 2][lrow] = b4.z;
        Bs[lcol + 3][lrow] = b4.w;
        __syncthreads();

#pragma unroll
        for (int kk = 0; kk < BK; kk++) {
            float ra[TM], rb[TN];
#pragma unroll
            for (int i = 0; i < TM; i++) ra[i] = As[kk][tm0 + i];
#pragma unroll
            for (int j = 0; j < TN; j++) rb[j] = Bs[kk][tn0 + j];
#pragma unroll
            for (int i = 0; i < TM; i++)
#pragma unroll
                for (int j = 0; j < TN; j++)
                    acc[i][j] += ra[i] * rb[j];
        }
        __syncthreads();
    }

    // epilogue: bias add + vectorized store
    const int gcol = bx * BN + tn0;
    float bvals[TN];
#pragma unroll
    for (int j = 0; j < TN; j++) bvals[j] = bias[gcol + j];

#pragma unroll
    for (int i = 0; i < TM; i++) {
        const size_t row = (size_t)(by * BM + tm0 + i);
        float4 o0, o1;
        o0.x = acc[i][0] + bvals[0];
        o0.y = acc[i][1] + bvals[1];
        o0.z = acc[i][2] + bvals[2];
        o0.w = acc[i][3] + bvals[3];
        o1.x = acc[i][4] + bvals[4];
        o1.y = acc[i][5] + bvals[5];
        o1.z = acc[i][6] + bvals[6];
        o1.w = acc[i][7] + bvals[7];
        *(float4*)(C + row * N + gcol)     = o0;
        *(float4*)(C + row * N + gcol + 4) = o1;
    }
}

// ---------------------------------------------------------------------------
// Flash attention, fp32, causal (mask read from device memory).
// Grid: (S/64, B*H). Block: 128 threads (4 warps; each warp owns 16 q rows).
// Q tile [64,64] smem; K tile transposed [64][65] (pad -> conflict-free);
// V tile [64,64]; P staged per-warp [16][64].
// Dynamic smem = (64*64 + 64*65 + 64*64 + 4*16*64) * 4 = 65792 B.
// ---------------------------------------------------------------------------
__global__ __launch_bounds__(128)
void attn_flash(const float* __restrict__ qkv, float* __restrict__ out,
                const int* __restrict__ maskp)
{
    constexpr int S = SEQ, D = DIM, H = HEADS, DH = DHEAD;
    constexpr int TQ = 64, TK = 64;
    constexpr int LD3 = 3 * D;

    const int qt = blockIdx.x;            // q tile index
    const int bh = blockIdx.y;
    const int b = bh / H, h = bh % H;
    const int tid = threadIdx.x;
    const int warp = tid >> 5, lane = tid & 31;
    const int mask = maskp[0];

    extern __shared__ float sm[];
    float* Qs = sm;                        // [64][64]
    float* Kt = Qs + 64 * 64;              // [64][65]
    float* Vs = Kt + 64 * 65;              // [64][64]
    float* Ps = Vs + 64 * 64;              // [4][16][64] (per-warp region)

    const float* qbase = qkv + ((size_t)b * S) * LD3 + h * DH;
    const float* kbase = qbase + D;
    const float* vbase = qbase + 2 * D;

    const int q0 = qt * TQ;

    // load Q tile
    for (int i = tid; i < TQ * DH; i += 128) {
        int r = i >> 6, d = i & 63;
        Qs[r * 64 + d] = qbase[(size_t)(q0 + r) * LD3 + d];
    }

    float m[16], l[16], acc0[16], acc1[16];
#pragma unroll
    for (int r = 0; r < 16; r++) { m[r] = -1e30f; l[r] = 0.f; acc0[r] = 0.f; acc1[r] = 0.f; }

    const int nkt = mask ? (qt + 1) : (S / TK);
    const float scale = 0.125f;  // 1/sqrt(64)
    float* Pw = Ps + warp * 16 * 64;

    for (int kt = 0; kt < nkt; kt++) {
        __syncthreads();   // covers Q load (first iter) + Vs reuse (later iters)
        const int k0 = kt * TK;
        for (int i = tid; i < TK * DH; i += 128) {
            int c = i >> 6, d = i & 63;
            float kv = kbase[(size_t)(k0 + c) * LD3 + d];
            float vv = vbase[(size_t)(k0 + c) * LD3 + d];
            Kt[d * 65 + c] = kv;
            Vs[c * 64 + d] = vv;
        }
        __syncthreads();

        // ---- scores: S[r][c] for c = lane, lane+32 ----
        float s0[16], s1[16];
#pragma unroll
        for (int r = 0; r < 16; r++) { s0[r] = 0.f; s1[r] = 0.f; }

#pragma unroll
        for (int d = 0; d < 64; d += 4) {
            float k10 = Kt[(d + 0) * 65 + lane];
            float k11 = Kt[(d + 1) * 65 + lane];
            float k12 = Kt[(d + 2) * 65 + lane];
            float k13 = Kt[(d + 3) * 65 + lane];
            float k20 = Kt[(d + 0) * 65 + 32 + lane];
            float k21 = Kt[(d + 1) * 65 + 32 + lane];
            float k22 = Kt[(d + 2) * 65 + 32 + lane];
            float k23 = Kt[(d + 3) * 65 + 32 + lane];
#pragma unroll
            for (int r = 0; r < 16; r++) {
                float4 q = *(const float4*)&Qs[(warp * 16 + r) * 64 + d];
                s0[r] += q.x * k10 + q.y * k11 + q.z * k12 + q.w * k13;
                s1[r] += q.x * k20 + q.y * k21 + q.z * k22 + q.w * k23;
            }
        }

        const bool diag = mask && (kt == qt);

        // ---- online softmax per row ----
#pragma unroll
        for (int r = 0; r < 16; r++) {
            float sa = s0[r] * scale;
            float sb = s1[r] * scale;
            if (diag) {
                int qg = warp * 16 + r;      // relative row index (q0 == k0)
                if (lane > qg)       sa = -1e30f;
                if (lane + 32 > qg)  sb = -1e30f;
            }
            float mt = fmaxf(sa, sb);
#pragma unroll
            for (int o = 16; o > 0; o >>= 1)
                mt = fmaxf(mt, __shfl_xor_sync(0xffffffffu, mt, o));
            float mn = fmaxf(m[r], mt);
            float alpha = __expf(m[r] - mn);
            float p0 = __expf(sa - mn);
            float p1 = __expf(sb - mn);
            float ls = p0 + p1;
#pragma unroll
            for (int o = 16; o > 0; o >>= 1)
                ls += __shfl_xor_sync(0xffffffffu, ls, o);
            m[r] = mn;
            l[r] = l[r] * alpha + ls;
            acc0[r] *= alpha;
            acc1[r] *= alpha;
            Pw[r * 64 + lane]      = p0;
            Pw[r * 64 + 32 + lane] = p1;
        }
        __syncwarp();

        // ---- O += P @ V ----
#pragma unroll
        for (int k = 0; k < 64; k += 4) {
            float v00 = Vs[(k + 0) * 64 + lane];
            float v01 = Vs[(k + 1) * 64 + lane];
            float v02 = Vs[(k + 2) * 64 + lane];
            float v03 = Vs[(k + 3) * 64 + lane];
            float v10 = Vs[(k + 0) * 64 + 32 + lane];
            float v11 = Vs[(k + 1) * 64 + 32 + lane];
            float v12 = Vs[(k + 2) * 64 + 32 + lane];
            float v13 = Vs[(k + 3) * 64 + 32 + lane];
#pragma unroll
            for (int r = 0; r < 16; r++) {
                float4 p = *(const float4*)&Pw[r * 64 + k];
                acc0[r] += p.x * v00 + p.y * v01 + p.z * v02 + p.w * v03;
                acc1[r] += p.x * v10 + p.y * v11 + p.z * v12 + p.w * v13;
            }
        }
    }

    // ---- write O (layout [B, S, D], head h at column h*DH) ----
#pragma unroll
    for (int r = 0; r < 16; r++) {
        float inv = 1.0f / l[r];
        size_t o = ((size_t)b * S + q0 + warp * 16 + r) * D + h * DH;
        out[o + lane]      = acc0[r] * inv;
        out[o + 32 + lane] = acc1[r] * inv;
    }
}

// ---------------------------------------------------------------------------
// Launch
// ---------------------------------------------------------------------------
extern "C" void kernel_launch(void* const* d_in, const int* in_sizes, int n_in,
                              void* d_out, int out_size)
{
    const float* x     = (const float*)d_in[0];
    const float* w_in  = (const float*)d_in[1];
    const float* b_in  = (const float*)d_in[2];
    const float* w_out = (const float*)d_in[3];
    const float* b_out = (const float*)d_in[4];
    const int*   mask  = (const int*)d_in[5];
    float* out = (float*)d_out;

    float* qkv = nullptr;
    float* attn = nullptr;
    cudaGetSymbolAddress((void**)&qkv, g_qkv);
    cudaGetSymbolAddress((void**)&attn, g_attn);

    const int M = BATCH * SEQ;      // 4096
    const int K = DIM;              // 1024
    const int N1 = 3 * DIM;         // 3072
    const int N2 = DIM;             // 1024

    // attention kernel needs > 48KB dynamic smem
    const int smem_bytes = (64 * 64 + 64 * 65 + 64 * 64 + 4 * 16 * 64) * 4;  // 65792
    cudaFuncSetAttribute(attn_flash, cudaFuncAttributeMaxDynamicSharedMemorySize, smem_bytes);

    // 1) QKV projection
    {
        dim3 grid(N1 / 128, M / 128);
        sgemm_nt_bias<<<grid, 256>>>(M, N1, K, x, w_in, b_in, qkv);
    }
    // 2) causal attention
    {
        dim3 grid(SEQ / 64, BATCH * HEADS);
        attn_flash<<<grid, 128, smem_bytes>>>(qkv, attn, mask);
    }
    // 3) output projection
    {
        dim3 grid(N2 / 128, M / 128);
        sgemm_nt_bias<<<grid, 256>>>(M, N2, K, attn, w_out, b_out, out);
    }
}

// round 3
// speedup vs baseline: 1.3761x; 1.3761x over previous
#include <cuda_runtime.h>
#include <cuda_bf16.h>
#include <cstdint>

// Problem constants
#define BATCH 2
#define SEQ   2048
#define DIM   1024
#define HEADS 16
#define DHEAD 64

// Scratch (device globals — no allocations allowed)
__device__ float g_qkv[(size_t)BATCH * SEQ * 3 * DIM];   // [B, S, 3D]
__device__ float g_attn[(size_t)BATCH * SEQ * DIM];      // [B, S, D]

// ---------------------------------------------------------------------------
// mma.sync helpers (portable PTX — no sm_103a-only instructions)
// ---------------------------------------------------------------------------
__device__ __forceinline__ uint32_t smem_u32(const void* p) {
    uint32_t a;
    asm("{ .reg .u64 t; cvta.to.shared.u64 t, %1; cvt.u32.u64 %0, t; }" : "=r"(a) : "l"(p));
    return a;
}

__device__ __forceinline__ void ldmatrix_x4(uint32_t* r, uint32_t addr) {
    asm volatile("ldmatrix.sync.aligned.m8n8.x4.shared.b16 {%0,%1,%2,%3}, [%4];"
                 : "=r"(r[0]), "=r"(r[1]), "=r"(r[2]), "=r"(r[3]) : "r"(addr));
}

__device__ __forceinline__ void mma_bf16(float* c, const uint32_t* a, const uint32_t* b) {
    asm volatile(
        "mma.sync.aligned.m16n8k16.row.col.f32.bf16.bf16.f32 "
        "{%0,%1,%2,%3}, {%4,%5,%6,%7}, {%8,%9}, {%0,%1,%2,%3};"
        : "+f"(c[0]), "+f"(c[1]), "+f"(c[2]), "+f"(c[3])
        : "r"(a[0]), "r"(a[1]), "r"(a[2]), "r"(a[3]), "r"(b[0]), "r"(b[1]));
}

// ---------------------------------------------------------------------------
// Tensor-core GEMM (bf16x3): C[m,n] = sum_k A[m,k]*B[n,k] + bias[n]
// Block tile 128x128, BK=32, 256 threads (8 warps, warp tile 64x32).
// smem tiles padded to stride 40 bf16 (80B rows): (5r+c)%8 is a permutation
// over 8 consecutive rows -> conflict-free ldmatrix.
// ---------------------------------------------------------------------------
#define TILE_B   10240            // 128 * 40 * 2 bytes
#define STAGE_B  (4 * TILE_B)     // Ah, Al, Bh, Bl
#define GEMM_SMEM (2 * STAGE_B)   // 81920 (double buffered)

__device__ __forceinline__ void cvt_store16(char* hi, char* lo,
                                            const float* v, int r, int halfk)
{
#pragma unroll
    for (int j = 0; j < 2; j++) {
        __align__(16) __nv_bfloat16 h[8];
        __align__(16) __nv_bfloat16 l[8];
#pragma unroll
        for (int i = 0; i < 8; i++) {
            float x = v[j * 8 + i];
            h[i] = __float2bfloat16(x);
            l[i] = __float2bfloat16(x - __bfloat162float(h[i]));
        }
        uint32_t off = (uint32_t)(r * 80 + (halfk / 8 + j) * 16);
        *(uint4*)(hi + off) = *(const uint4*)h;
        *(uint4*)(lo + off) = *(const uint4*)l;
    }
}

__global__ __launch_bounds__(256)
void gemm_mma_bias(int M, int N, int K,
                   const float* __restrict__ A,
                   const float* __restrict__ B,
                   const float* __restrict__ bias,
                   float* __restrict__ C)
{
    extern __shared__ char smem[];
    const uint32_t sbase = smem_u32(smem);

    const int tid  = threadIdx.x;
    const int wid  = tid >> 5;
    const int lane = tid & 31;
    const int bx = blockIdx.x;          // N tile
    const int by = blockIdx.y;          // M tile
    const int warpM = wid & 1;          // 2 warps along M (64 each)
    const int warpN = wid >> 1;         // 4 warps along N (32 each)

    // global load mapping: row = tid/2, 16 consecutive k per thread
    const int gr = tid >> 1;
    const int gh = (tid & 1) * 16;
    const float* Ag = A + (size_t)(by * 128 + gr) * K + gh;
    const float* Bg = B + (size_t)(bx * 128 + gr) * K + gh;

    float acc[4][4][4];
#pragma unroll
    for (int i = 0; i < 4; i++)
#pragma unroll
        for (int j = 0; j < 4; j++)
#pragma unroll
            for (int v = 0; v < 4; v++) acc[i][j][v] = 0.f;

    const int KC = K >> 5;   // chunks of 32

    // prologue: stage 0
    {
        float av[16], bv[16];
#pragma unroll
        for (int v = 0; v < 4; v++) {
            *(float4*)(av + v * 4) = *(const float4*)(Ag + v * 4);
            *(float4*)(bv + v * 4) = *(const float4*)(Bg + v * 4);
        }
        cvt_store16(smem + 0 * TILE_B, smem + 1 * TILE_B, av, gr, gh);
        cvt_store16(smem + 2 * TILE_B, smem + 3 * TILE_B, bv, gr, gh);
    }
    __syncthreads();

    // ldmatrix lane addressing (fixed per thread)
    const int aRow = warpM * 64 + ((lane >> 3) & 1) * 8 + (lane & 7);
    const int aColHalf = (lane >> 4) * 16;            // k-half byte offset
    const int bRow = warpN * 32 + (lane >> 4) * 8 + (lane & 7);
    const int bColHalf = ((lane >> 3) & 1) * 16;

    for (int kt = 0; kt < KC; kt++) {
        const int cur = kt & 1;
        const uint32_t sAh = sbase + cur * STAGE_B;
        const uint32_t sAl = sAh + TILE_B;
        const uint32_t sBh = sAh + 2 * TILE_B;
        const uint32_t sBl = sAh + 3 * TILE_B;

        // prefetch next chunk into registers
        float av[16], bv[16];
        const bool pf = (kt + 1 < KC);
        if (pf) {
            const float* Ap = Ag + (kt + 1) * 32;
            const float* Bp = Bg + (kt + 1) * 32;
#pragma unroll
            for (int v = 0; v < 4; v++) {
                *(float4*)(av + v * 4) = *(const float4*)(Ap + v * 4);
                *(float4*)(bv + v * 4) = *(const float4*)(Bp + v * 4);
            }
        }

        // compute on current stage
#pragma unroll
        for (int ks = 0; ks < 2; ks++) {
            uint32_t ah[4][4], al[4][4], bh[4][2], bl[4][2];
            const uint32_t acol = (uint32_t)(ks * 32 + aColHalf);
            const uint32_t bcol = (uint32_t)(ks * 32 + bColHalf);
#pragma unroll
            for (int mt = 0; mt < 4; mt++) {
                uint32_t off = (uint32_t)((aRow + mt * 16) * 80) + acol;
                ldmatrix_x4(ah[mt], sAh + off);
                ldmatrix_x4(al[mt], sAl + off);
            }
#pragma unroll
            for (int pr = 0; pr < 2; pr++) {
                uint32_t off = (uint32_t)((bRow + pr * 16) * 80) + bcol;
                uint32_t r0[4], r1[4];
                ldmatrix_x4(r0, sBh + off);
                ldmatrix_x4(r1, sBl + off);
                bh[pr * 2 + 0][0] = r0[0]; bh[pr * 2 + 0][1] = r0[1];
                bh[pr * 2 + 1][0] = r0[2]; bh[pr * 2 + 1][1] = r0[3];
                bl[pr * 2 + 0][0] = r1[0]; bl[pr * 2 + 0][1] = r1[1];
                bl[pr * 2 + 1][0] = r1[2]; bl[pr * 2 + 1][1] = r1[3];
            }
#pragma unroll
            for (int mt = 0; mt < 4; mt++)
#pragma unroll
                for (int nt = 0; nt < 4; nt++) {
                    mma_bf16(acc[mt][nt], ah[mt], bh[nt]);
                    mma_bf16(acc[mt][nt], ah[mt], bl[nt]);
                    mma_bf16(acc[mt][nt], al[mt], bh[nt]);
                }
        }

        // store prefetched chunk to the other stage
        if (pf) {
            char* base = smem + ((kt + 1) & 1) * STAGE_B;
            cvt_store16(base + 0 * TILE_B, base + 1 * TILE_B, av, gr, gh);
            cvt_store16(base + 2 * TILE_B, base + 3 * TILE_B, bv, gr, gh);
        }
        __syncthreads();
    }

    // epilogue: bias + store
    const int crow = by * 128 + warpM * 64 + (lane >> 2);
    const int ccol = bx * 128 + warpN * 32 + (lane & 3) * 2;
#pragma unroll
    for (int nt = 0; nt < 4; nt++) {
        const int col = ccol + nt * 8;
        const float b0 = bias[col], b1 = bias[col + 1];
#pragma unroll
        for (int mt = 0; mt < 4; mt++) {
            const int r0 = crow + mt * 16;
            float2 o0 = make_float2(acc[mt][nt][0] + b0, acc[mt][nt][1] + b1);
            float2 o1 = make_float2(acc[mt][nt][2] + b0, acc[mt][nt][3] + b1);
            *(float2*)(C + (size_t)r0 * N + col)       = o0;
            *(float2*)(C + (size_t)(r0 + 8) * N + col) = o1;
        }
    }
}

// ---------------------------------------------------------------------------
// Flash attention, fp32, causal (unchanged — passes at 1e-6).
// ---------------------------------------------------------------------------
__global__ __launch_bounds__(128)
void attn_flash(const float* __restrict__ qkv, float* __restrict__ out,
                const int* __restrict__ maskp)
{
    constexpr int S = SEQ, D = DIM, H = HEADS, DH = DHEAD;
    constexpr int TQ = 64, TK = 64;
    constexpr int LD3 = 3 * D;

    const int qt = blockIdx.x;
    const int bh = blockIdx.y;
    const int b = bh / H, h = bh % H;
    const int tid = threadIdx.x;
    const int warp = tid >> 5, lane = tid & 31;
    const int mask = maskp[0];

    extern __shared__ float sm[];
    float* Qs = sm;                        // [64][64]
    float* Kt = Qs + 64 * 64;              // [64][65]
    float* Vs = Kt + 64 * 65;              // [64][64]
    float* Ps = Vs + 64 * 64;              // [4][16][64]

    const float* qbase = qkv + ((size_t)b * S) * LD3 + h * DH;
    const float* kbase = qbase + D;
    const float* vbase = qbase + 2 * D;

    const int q0 = qt * TQ;

    for (int i = tid; i < TQ * DH; i += 128) {
        int r = i >> 6, d = i & 63;
        Qs[r * 64 + d] = qbase[(size_t)(q0 + r) * LD3 + d];
    }

    float m[16], l[16], acc0[16], acc1[16];
#pragma unroll
    for (int r = 0; r < 16; r++) { m[r] = -1e30f; l[r] = 0.f; acc0[r] = 0.f; acc1[r] = 0.f; }

    const int nkt = mask ? (qt + 1) : (S / TK);
    const float scale = 0.125f;
    float* Pw = Ps + warp * 16 * 64;

    for (int kt = 0; kt < nkt; kt++) {
        __syncthreads();
        const int k0 = kt * TK;
        for (int i = tid; i < TK * DH; i += 128) {
            int c = i >> 6, d = i & 63;
            float kv = kbase[(size_t)(k0 + c) * LD3 + d];
            float vv = vbase[(size_t)(k0 + c) * LD3 + d];
            Kt[d * 65 + c] = kv;
            Vs[c * 64 + d] = vv;
        }
        __syncthreads();

        float s0[16], s1[16];
#pragma unroll
        for (int r = 0; r < 16; r++) { s0[r] = 0.f; s1[r] = 0.f; }

#pragma unroll
        for (int d = 0; d < 64; d += 4) {
            float k10 = Kt[(d + 0) * 65 + lane];
            float k11 = Kt[(d + 1) * 65 + lane];
            float k12 = Kt[(d + 2) * 65 + lane];
            float k13 = Kt[(d + 3) * 65 + lane];
            float k20 = Kt[(d + 0) * 65 + 32 + lane];
            float k21 = Kt[(d + 1) * 65 + 32 + lane];
            float k22 = Kt[(d + 2) * 65 + 32 + lane];
            float k23 = Kt[(d + 3) * 65 + 32 + lane];
#pragma unroll
            for (int r = 0; r < 16; r++) {
                float4 q = *(const float4*)&Qs[(warp * 16 + r) * 64 + d];
                s0[r] += q.x * k10 + q.y * k11 + q.z * k12 + q.w * k13;
                s1[r] += q.x * k20 + q.y * k21 + q.z * k22 + q.w * k23;
            }
        }

        const bool diag = mask && (kt == qt);

#pragma unroll
        for (int r = 0; r < 16; r++) {
            float sa = s0[r] * scale;
            float sb = s1[r] * scale;
            if (diag) {
                int qg = warp * 16 + r;
                if (lane > qg)       sa = -1e30f;
                if (lane + 32 > qg)  sb = -1e30f;
            }
            float mt = fmaxf(sa, sb);
#pragma unroll
            for (int o = 16; o > 0; o >>= 1)
                mt = fmaxf(mt, __shfl_xor_sync(0xffffffffu, mt, o));
            float mn = fmaxf(m[r], mt);
            float alpha = __expf(m[r] - mn);
            float p0 = __expf(sa - mn);
            float p1 = __expf(sb - mn);
            float ls = p0 + p1;
#pragma unroll
            for (int o = 16; o > 0; o >>= 1)
                ls += __shfl_xor_sync(0xffffffffu, ls, o);
            m[r] = mn;
            l[r] = l[r] * alpha + ls;
            acc0[r] *= alpha;
            acc1[r] *= alpha;
            Pw[r * 64 + lane]      = p0;
            Pw[r * 64 + 32 + lane] = p1;
        }
        __syncwarp();

#pragma unroll
        for (int k = 0; k < 64; k += 4) {
            float v00 = Vs[(k + 0) * 64 + lane];
            float v01 = Vs[(k + 1) * 64 + lane];
            float v02 = Vs[(k + 2) * 64 + lane];
            float v03 = Vs[(k + 3) * 64 + lane];
            float v10 = Vs[(k + 0) * 64 + 32 + lane];
            float v11 = Vs[(k + 1) * 64 + 32 + lane];
            float v12 = Vs[(k + 2) * 64 + 32 + lane];
            float v13 = Vs[(k + 3) * 64 + 32 + lane];
#pragma unroll
            for (int r = 0; r < 16; r++) {
                float4 p = *(const float4*)&Pw[r * 64 + k];
                acc0[r] += p.x * v00 + p.y * v01 + p.z * v02 + p.w * v03;
                acc1[r] += p.x * v10 + p.y * v11 + p.z * v12 + p.w * v13;
            }
        }
    }

#pragma unroll
    for (int r = 0; r < 16; r++) {
        float inv = 1.0f / l[r];
        size_t o = ((size_t)b * S + q0 + warp * 16 + r) * D + h * DH;
        out[o + lane]      = acc0[r] * inv;
        out[o + 32 + lane] = acc1[r] * inv;
    }
}

// ---------------------------------------------------------------------------
// Launch
// ---------------------------------------------------------------------------
extern "C" void kernel_launch(void* const* d_in, const int* in_sizes, int n_in,
                              void* d_out, int out_size)
{
    const float* x     = (const float*)d_in[0];
    const float* w_in  = (const float*)d_in[1];
    const float* b_in  = (const float*)d_in[2];
    const float* w_out = (const float*)d_in[3];
    const float* b_out = (const float*)d_in[4];
    const int*   mask  = (const int*)d_in[5];
    float* out = (float*)d_out;

    float* qkv = nullptr;
    float* attn = nullptr;
    cudaGetSymbolAddress((void**)&qkv, g_qkv);
    cudaGetSymbolAddress((void**)&attn, g_attn);

    const int M = BATCH * SEQ;      // 4096
    const int K = DIM;              // 1024
    const int N1 = 3 * DIM;         // 3072
    const int N2 = DIM;             // 1024

    cudaFuncSetAttribute(gemm_mma_bias, cudaFuncAttributeMaxDynamicSharedMemorySize, GEMM_SMEM);
    const int attn_smem = (64 * 64 + 64 * 65 + 64 * 64 + 4 * 16 * 64) * 4;  // 65792
    cudaFuncSetAttribute(attn_flash, cudaFuncAttributeMaxDynamicSharedMemorySize, attn_smem);

    // 1) QKV projection (tensor cores via mma.sync, bf16x3)
    {
        dim3 grid(N1 / 128, M / 128);
        gemm_mma_bias<<<grid, 256, GEMM_SMEM>>>(M, N1, K, x, w_in, b_in, qkv);
    }
    // 2) causal attention
    {
        dim3 grid(SEQ / 64, BATCH * HEADS);
        attn_flash<<<grid, 128, attn_smem>>>(qkv, attn, mask);
    }
    // 3) output projection
    {
        dim3 grid(N2 / 128, M / 128);
        gemm_mma_bias<<<grid, 256, GEMM_SMEM>>>(M, N2, K, attn, w_out, b_out, out);
    }
}

// round 5
// speedup vs baseline: 2.8741x; 2.0885x over previous
#include <cuda_runtime.h>
#include <cuda_bf16.h>
#include <cstdint>

// Problem constants
#define BATCH 2
#define SEQ   2048
#define DIM   1024
#define HEADS 16
#define DHEAD 64

// Scratch (device globals — no allocations allowed)
__device__ float g_qkv[(size_t)BATCH * SEQ * 3 * DIM];   // [B, S, 3D]
__device__ float g_attn[(size_t)BATCH * SEQ * DIM];      // [B, S, D]

// ---------------------------------------------------------------------------
// mma.sync helpers (portable PTX)
// ---------------------------------------------------------------------------
__device__ __forceinline__ uint32_t smem_u32(const void* p) {
    uint32_t a;
    asm("{ .reg .u64 t; cvta.to.shared.u64 t, %1; cvt.u32.u64 %0, t; }" : "=r"(a) : "l"(p));
    return a;
}

__device__ __forceinline__ void ldmatrix_x4(uint32_t* r, uint32_t addr) {
    asm volatile("ldmatrix.sync.aligned.m8n8.x4.shared.b16 {%0,%1,%2,%3}, [%4];"
                 : "=r"(r[0]), "=r"(r[1]), "=r"(r[2]), "=r"(r[3]) : "r"(addr));
}

__device__ __forceinline__ void ldmatrix_x4_trans(uint32_t* r, uint32_t addr) {
    asm volatile("ldmatrix.sync.aligned.m8n8.x4.trans.shared.b16 {%0,%1,%2,%3}, [%4];"
                 : "=r"(r[0]), "=r"(r[1]), "=r"(r[2]), "=r"(r[3]) : "r"(addr));
}

__device__ __forceinline__ void mma_bf16(float* c, const uint32_t* a, const uint32_t* b) {
    asm volatile(
        "mma.sync.aligned.m16n8k16.row.col.f32.bf16.bf16.f32 "
        "{%0,%1,%2,%3}, {%4,%5,%6,%7}, {%8,%9}, {%0,%1,%2,%3};"
        : "+f"(c[0]), "+f"(c[1]), "+f"(c[2]), "+f"(c[3])
        : "r"(a[0]), "r"(a[1]), "r"(a[2]), "r"(a[3]), "r"(b[0]), "r"(b[1]));
}

__device__ __forceinline__ uint32_t pack_bf16(float lo, float hi) {
    __nv_bfloat162 t = __float22bfloat162_rn(make_float2(lo, hi));
    return *(uint32_t*)&t;
}

// Convert 16 floats -> bf16 hi/lo, store at padded row (row stride = `stride` bytes)
__device__ __forceinline__ void cvt_store16(char* hi, char* lo,
                                            const float* v, int r, int halfk, int stride)
{
#pragma unroll
    for (int j = 0; j < 2; j++) {
        __align__(16) __nv_bfloat16 h[8];
        __align__(16) __nv_bfloat16 l[8];
#pragma unroll
        for (int i = 0; i < 8; i++) {
            float x = v[j * 8 + i];
            h[i] = __float2bfloat16(x);
            l[i] = __float2bfloat16(x - __bfloat162float(h[i]));
        }
        uint32_t off = (uint32_t)(r * stride + halfk * 2 + j * 16);
        *(uint4*)(hi + off) = *(const uint4*)h;
        *(uint4*)(lo + off) = *(const uint4*)l;
    }
}

// ---------------------------------------------------------------------------
// Tensor-core GEMM (bf16x3): unchanged from Round 3 (304us QKV). Stride 80.
// ---------------------------------------------------------------------------
#define TILE_B   10240
#define STAGE_B  (4 * TILE_B)
#define GEMM_SMEM (2 * STAGE_B)

__global__ __launch_bounds__(256)
void gemm_mma_bias(int M, int N, int K,
                   const float* __restrict__ A,
                   const float* __restrict__ B,
                   const float* __restrict__ bias,
                   float* __restrict__ C)
{
    extern __shared__ char smem[];
    const uint32_t sbase = smem_u32(smem);

    const int tid  = threadIdx.x;
    const int wid  = tid >> 5;
    const int lane = tid & 31;
    const int bx = blockIdx.x;
    const int by = blockIdx.y;
    const int warpM = wid & 1;
    const int warpN = wid >> 1;

    const int gr = tid >> 1;
    const int gh = (tid & 1) * 16;
    const float* Ag = A + (size_t)(by * 128 + gr) * K + gh;
    const float* Bg = B + (size_t)(bx * 128 + gr) * K + gh;

    float acc[4][4][4];
#pragma unroll
    for (int i = 0; i < 4; i++)
#pragma unroll
        for (int j = 0; j < 4; j++)
#pragma unroll
            for (int v = 0; v < 4; v++) acc[i][j][v] = 0.f;

    const int KC = K >> 5;

    {
        float av[16], bv[16];
#pragma unroll
        for (int v = 0; v < 4; v++) {
            *(float4*)(av + v * 4) = *(const float4*)(Ag + v * 4);
            *(float4*)(bv + v * 4) = *(const float4*)(Bg + v * 4);
        }
        cvt_store16(smem + 0 * TILE_B, smem + 1 * TILE_B, av, gr, gh, 80);
        cvt_store16(smem + 2 * TILE_B, smem + 3 * TILE_B, bv, gr, gh, 80);
    }
    __syncthreads();

    const int aRow = warpM * 64 + ((lane >> 3) & 1) * 8 + (lane & 7);
    const int aColHalf = (lane >> 4) * 16;
    const int bRow = warpN * 32 + (lane >> 4) * 8 + (lane & 7);
    const int bColHalf = ((lane >> 3) & 1) * 16;

    for (int kt = 0; kt < KC; kt++) {
        const int cur = kt & 1;
        const uint32_t sAh = sbase + cur * STAGE_B;
        const uint32_t sAl = sAh + TILE_B;
        const uint32_t sBh = sAh + 2 * TILE_B;
        const uint32_t sBl = sAh + 3 * TILE_B;

        float av[16], bv[16];
        const bool pf = (kt + 1 < KC);
        if (pf) {
            const float* Ap = Ag + (kt + 1) * 32;
            const float* Bp = Bg + (kt + 1) * 32;
#pragma unroll
            for (int v = 0; v < 4; v++) {
                *(float4*)(av + v * 4) = *(const float4*)(Ap + v * 4);
                *(float4*)(bv + v * 4) = *(const float4*)(Bp + v * 4);
            }
        }

#pragma unroll
        for (int ks = 0; ks < 2; ks++) {
            uint32_t ah[4][4], al[4][4], bh[4][2], bl[4][2];
            const uint32_t acol = (uint32_t)(ks * 32 + aColHalf);
            const uint32_t bcol = (uint32_t)(ks * 32 + bColHalf);
#pragma unroll
            for (int mt = 0; mt < 4; mt++) {
                uint32_t off = (uint32_t)((aRow + mt * 16) * 80) + acol;
                ldmatrix_x4(ah[mt], sAh + off);
                ldmatrix_x4(al[mt], sAl + off);
            }
#pragma unroll
            for (int pr = 0; pr < 2; pr++) {
                uint32_t off = (uint32_t)((bRow + pr * 16) * 80) + bcol;
                uint32_t r0[4], r1[4];
                ldmatrix_x4(r0, sBh + off);
                ldmatrix_x4(r1, sBl + off);
                bh[pr * 2 + 0][0] = r0[0]; bh[pr * 2 + 0][1] = r0[1];
                bh[pr * 2 + 1][0] = r0[2]; bh[pr * 2 + 1][1] = r0[3];
                bl[pr * 2 + 0][0] = r1[0]; bl[pr * 2 + 0][1] = r1[1];
                bl[pr * 2 + 1][0] = r1[2]; bl[pr * 2 + 1][1] = r1[3];
            }
#pragma unroll
            for (int mt = 0; mt < 4; mt++)
#pragma unroll
                for (int nt = 0; nt < 4; nt++) {
                    mma_bf16(acc[mt][nt], ah[mt], bh[nt]);
                    mma_bf16(acc[mt][nt], ah[mt], bl[nt]);
                    mma_bf16(acc[mt][nt], al[mt], bh[nt]);
                }
        }

        if (pf) {
            char* base = smem + ((kt + 1) & 1) * STAGE_B;
            cvt_store16(base + 0 * TILE_B, base + 1 * TILE_B, av, gr, gh, 80);
            cvt_store16(base + 2 * TILE_B, base + 3 * TILE_B, bv, gr, gh, 80);
        }
        __syncthreads();
    }

    const int crow = by * 128 + warpM * 64 + (lane >> 2);
    const int ccol = bx * 128 + warpN * 32 + (lane & 3) * 2;
#pragma unroll
    for (int nt = 0; nt < 4; nt++) {
        const int col = ccol + nt * 8;
        const float b0 = bias[col], b1 = bias[col + 1];
#pragma unroll
        for (int mt = 0; mt < 4; mt++) {
            const int r0 = crow + mt * 16;
            float2 o0 = make_float2(acc[mt][nt][0] + b0, acc[mt][nt][1] + b1);
            float2 o1 = make_float2(acc[mt][nt][2] + b0, acc[mt][nt][3] + b1);
            *(float2*)(C + (size_t)r0 * N + col)       = o0;
            *(float2*)(C + (size_t)(r0 + 8) * N + col) = o1;
        }
    }
}

// ---------------------------------------------------------------------------
// Flash attention with mma.sync (bf16x3 compensated), causal.
// Grid: (SEQ/128, B*H). Block 256 (8 warps x m16 q-rows).
// Row stride 144 B (72 bf16): (9r+c)/16 mod 8 = (r+c) mod 8 -> conflict-free.
// smem 36864 B. Q staging: [Qh 18432 | Ql 18432] (consumed into registers).
// Per-tile: [Kh 9216 | Kl 9216 | Vh 9216 | Vl 9216].
// ---------------------------------------------------------------------------
#define ASTR 144
#define KV_T 9216                  // 64 * 144
#define ATT_SMEM 36864

__global__ __launch_bounds__(256, 1)
void attn_mma(const float* __restrict__ qkv, float* __restrict__ out,
              const int* __restrict__ maskp)
{
    extern __shared__ char sm[];
    const uint32_t sb = smem_u32(sm);
    const int tid = threadIdx.x, wid = tid >> 5, lane = tid & 31;
    const int qt = blockIdx.x, bh = blockIdx.y;
    const int b = bh >> 4, h = bh & 15;
    const int mask = maskp[0];
    const int q0 = qt * 128;
    const size_t LD3 = 3 * DIM;
    const float* qb = qkv + (size_t)b * SEQ * LD3 + h * 64;
    const float* kb = qb + DIM;
    const float* vb = qb + 2 * DIM;

    // ---- stage Q (scaled by 1/8), convert hi/lo ----
    {
        const int r = tid >> 1, hf = (tid & 1) * 32;
        const float* src = qb + (size_t)(q0 + r) * LD3 + hf;
        float v[32];
#pragma unroll
        for (int i = 0; i < 8; i++) {
            float4 f = *(const float4*)(src + i * 4);
            v[i * 4 + 0] = f.x * 0.125f; v[i * 4 + 1] = f.y * 0.125f;
            v[i * 4 + 2] = f.z * 0.125f; v[i * 4 + 3] = f.w * 0.125f;
        }
        cvt_store16(sm, sm + 18432, v, r, hf, ASTR);
        cvt_store16(sm, sm + 18432, v + 16, r, hf + 16, ASTR);
    }
    __syncthreads();

    // ---- Q A-fragments into registers (held all kernel) ----
    uint32_t qh[4][4], ql[4][4];
#pragma unroll
    for (int j = 0; j < 4; j++) {
        uint32_t addr = sb + (uint32_t)((wid * 16 + (lane & 15)) * ASTR
                       + (j * 16 + ((lane >> 4) & 1) * 8) * 2);
        ldmatrix_x4(qh[j], addr);
        ldmatrix_x4(ql[j], addr + 18432);
    }
    __syncthreads();

    float o[8][4];
#pragma unroll
    for (int t = 0; t < 8; t++)
#pragma unroll
        for (int v = 0; v < 4; v++) o[t][v] = 0.f;
    float m0 = -1e30f, m1 = -1e30f, l0 = 0.f, l1 = 0.f;

    const int nkt_load = mask ? (2 * qt + 2) : (SEQ / 64);
    const int nkt_w    = mask ? (2 * qt + 1 + (wid >= 4 ? 1 : 0)) : (SEQ / 64);

    // fragment addressing (constant per thread)
    const uint32_t kfrag_base = sb + (uint32_t)(
        (((lane >> 4) << 3) + (lane & 7)) * ASTR + (((lane >> 3) & 1) * 8) * 2);
    const uint32_t vfrag_base = sb + 2 * KV_T + (uint32_t)(
        ((((lane >> 3) & 1) * 8 + (lane & 7)) * ASTR) + (((lane >> 4) & 1) * 8) * 2);

    for (int kt = 0; kt < nkt_load; kt++) {
        __syncthreads();
        // ---- load & convert K/V tile: threads 0-127 -> K, 128-255 -> V ----
        {
            const int tt = tid & 127;
            const int r = tt >> 1, hf = (tt & 1) * 32;
            const float* src = (tid < 128 ? kb : vb) + (size_t)(kt * 64 + r) * LD3 + hf;
            char* hi = sm + (tid < 128 ? 0 : 2 * KV_T);
            float v[32];
#pragma unroll
            for (int i = 0; i < 8; i++)
                *(float4*)(v + i * 4) = *(const float4*)(src + i * 4);
            cvt_store16(hi, hi + KV_T, v, r, hf, ASTR);
            cvt_store16(hi, hi + KV_T, v + 16, r, hf + 16, ASTR);
        }
        __syncthreads();
        if (kt >= nkt_w) continue;

        // ---- scores = Q K^T (bf16x3) ----
        float sc[8][4];
#pragma unroll
        for (int t = 0; t < 8; t++)
#pragma unroll
            for (int v = 0; v < 4; v++) sc[t][v] = 0.f;

#pragma unroll
        for (int j = 0; j < 4; j++) {
#pragma unroll
            for (int t = 0; t < 4; t++) {
                uint32_t addr = kfrag_base + (uint32_t)(t * 16 * ASTR + j * 32);
                uint32_t rh[4], rl[4];
                ldmatrix_x4(rh, addr);
                ldmatrix_x4(rl, addr + KV_T);
                mma_bf16(sc[2 * t + 0], qh[j], rh);       // hh
                mma_bf16(sc[2 * t + 1], qh[j], rh + 2);
                mma_bf16(sc[2 * t + 0], qh[j], rl);       // hl
                mma_bf16(sc[2 * t + 1], qh[j], rl + 2);
                mma_bf16(sc[2 * t + 0], ql[j], rh);       // lh
                mma_bf16(sc[2 * t + 1], ql[j], rh + 2);
            }
        }

        // ---- online softmax ----
        const int row0 = q0 + wid * 16 + (lane >> 2);
        const int row1 = row0 + 8;
        const int cbase = kt * 64 + (lane & 3) * 2;
        const bool needmask = mask && (kt * 64 + 63 > q0 + wid * 16);
        if (needmask) {
#pragma unroll
            for (int t = 0; t < 8; t++) {
                int c0 = cbase + t * 8, c1 = c0 + 1;
                if (c0 > row0) sc[t][0] = -1e30f;
                if (c1 > row0) sc[t][1] = -1e30f;
                if (c0 > row1) sc[t][2] = -1e30f;
                if (c1 > row1) sc[t][3] = -1e30f;
            }
        }
        float mt0 = -1e30f, mt1 = -1e30f;
#pragma unroll
        for (int t = 0; t < 8; t++) {
            mt0 = fmaxf(mt0, fmaxf(sc[t][0], sc[t][1]));
            mt1 = fmaxf(mt1, fmaxf(sc[t][2], sc[t][3]));
        }
        mt0 = fmaxf(mt0, __shfl_xor_sync(0xffffffffu, mt0, 1));
        mt0 = fmaxf(mt0, __shfl_xor_sync(0xffffffffu, mt0, 2));
        mt1 = fmaxf(mt1, __shfl_xor_sync(0xffffffffu, mt1, 1));
        mt1 = fmaxf(mt1, __shfl_xor_sync(0xffffffffu, mt1, 2));
        const float mn0 = fmaxf(m0, mt0), mn1 = fmaxf(m1, mt1);
        const float a0 = __expf(m0 - mn0), a1 = __expf(m1 - mn1);

        uint32_t ph[8][2], pl[8][2];
        float s0 = 0.f, s1 = 0.f;
#pragma unroll
        for (int t = 0; t < 8; t++) {
            float p00 = __expf(sc[t][0] - mn0);
            float p01 = __expf(sc[t][1] - mn0);
            float p10 = __expf(sc[t][2] - mn1);
            float p11 = __expf(sc[t][3] - mn1);
            s0 += p00 + p01;
            s1 += p10 + p11;
            ph[t][0] = pack_bf16(p00, p01);
            ph[t][1] = pack_bf16(p10, p11);
            float h00 = __bfloat162float(__float2bfloat16(p00));
            float h01 = __bfloat162float(__float2bfloat16(p01));
            float h10 = __bfloat162float(__float2bfloat16(p10));
            float h11 = __bfloat162float(__float2bfloat16(p11));
            pl[t][0] = pack_bf16(p00 - h00, p01 - h01);
            pl[t][1] = pack_bf16(p10 - h10, p11 - h11);
        }
        s0 += __shfl_xor_sync(0xffffffffu, s0, 1);
        s0 += __shfl_xor_sync(0xffffffffu, s0, 2);
        s1 += __shfl_xor_sync(0xffffffffu, s1, 1);
        s1 += __shfl_xor_sync(0xffffffffu, s1, 2);
        m0 = mn0; m1 = mn1;
        l0 = l0 * a0 + s0;
        l1 = l1 * a1 + s1;
#pragma unroll
        for (int t = 0; t < 8; t++) {
            o[t][0] *= a0; o[t][1] *= a0;
            o[t][2] *= a1; o[t][3] *= a1;
        }

        // ---- O += P V (bf16x3) ----
#pragma unroll
        for (int j = 0; j < 4; j++) {
            uint32_t afh[4] = { ph[2*j][0], ph[2*j][1], ph[2*j+1][0], ph[2*j+1][1] };
            uint32_t afl[4] = { pl[2*j][0], pl[2*j][1], pl[2*j+1][0], pl[2*j+1][1] };
#pragma unroll
            for (int t = 0; t < 4; t++) {
                uint32_t addr = vfrag_base + (uint32_t)(j * 16 * ASTR + t * 32);
                uint32_t rh[4], rl[4];
                ldmatrix_x4_trans(rh, addr);
                ldmatrix_x4_trans(rl, addr + KV_T);
                mma_bf16(o[2 * t + 0], afh, rh);
                mma_bf16(o[2 * t + 1], afh, rh + 2);
                mma_bf16(o[2 * t + 0], afh, rl);
                mma_bf16(o[2 * t + 1], afh, rl + 2);
                mma_bf16(o[2 * t + 0], afl, rh);
                mma_bf16(o[2 * t + 1], afl, rh + 2);
            }
        }
    }

    // ---- write O ----
    const float il0 = 1.0f / l0, il1 = 1.0f / l1;
    const int orow = q0 + wid * 16 + (lane >> 2);
    float* ob = out + ((size_t)b * SEQ + orow) * DIM + h * 64 + (lane & 3) * 2;
#pragma unroll
    for (int t = 0; t < 8; t++) {
        *(float2*)(ob + t * 8)            = make_float2(o[t][0] * il0, o[t][1] * il0);
        *(float2*)(ob + 8 * DIM + t * 8)  = make_float2(o[t][2] * il1, o[t][3] * il1);
    }
}

// ---------------------------------------------------------------------------
// Launch
// ---------------------------------------------------------------------------
extern "C" void kernel_launch(void* const* d_in, const int* in_sizes, int n_in,
                              void* d_out, int out_size)
{
    const float* x     = (const float*)d_in[0];
    const float* w_in  = (const float*)d_in[1];
    const float* b_in  = (const float*)d_in[2];
    const float* w_out = (const float*)d_in[3];
    const float* b_out = (const float*)d_in[4];
    const int*   mask  = (const int*)d_in[5];
    float* out = (float*)d_out;

    float* qkv = nullptr;
    float* attn = nullptr;
    cudaGetSymbolAddress((void**)&qkv, g_qkv);
    cudaGetSymbolAddress((void**)&attn, g_attn);

    const int M = BATCH * SEQ;      // 4096
    const int K = DIM;              // 1024
    const int N1 = 3 * DIM;         // 3072
    const int N2 = DIM;             // 1024

    cudaFuncSetAttribute(gemm_mma_bias, cudaFuncAttributeMaxDynamicSharedMemorySize, GEMM_SMEM);

    // 1) QKV projection
    {
        dim3 grid(N1 / 128, M / 128);
        gemm_mma_bias<<<grid, 256, GEMM_SMEM>>>(M, N1, K, x, w_in, b_in, qkv);
    }
    // 2) causal attention (tensor cores)
    {
        dim3 grid(SEQ / 128, BATCH * HEADS);
        attn_mma<<<grid, 256, ATT_SMEM>>>(qkv, attn, mask);
    }
    // 3) output projection
    {
        dim3 grid(N2 / 128, M / 128);
        gemm_mma_bias<<<grid, 256, GEMM_SMEM>>>(M, N2, K, attn, w_out, b_out, out);
    }
}

// round 6
// speedup vs baseline: 3.3760x; 1.1746x over previous
#include <cuda_runtime.h>
#include <cuda_bf16.h>
#include <cstdint>

// Problem constants
#define BATCH 2
#define SEQ   2048
#define DIM   1024
#define HEADS 16
#define DHEAD 64

typedef __nv_bfloat16 bf16;

// Scratch (device globals — no allocations allowed)
__device__ bf16 g_xh [(size_t)BATCH * SEQ * DIM];
__device__ bf16 g_xl [(size_t)BATCH * SEQ * DIM];
__device__ bf16 g_wih[(size_t)3 * DIM * DIM];
__device__ bf16 g_wil[(size_t)3 * DIM * DIM];
__device__ bf16 g_woh[(size_t)DIM * DIM];
__device__ bf16 g_wol[(size_t)DIM * DIM];
__device__ bf16 g_qkvh[(size_t)BATCH * SEQ * 3 * DIM];
__device__ bf16 g_qkvl[(size_t)BATCH * SEQ * 3 * DIM];
__device__ bf16 g_ah [(size_t)BATCH * SEQ * DIM];
__device__ bf16 g_al [(size_t)BATCH * SEQ * DIM];

// ---------------------------------------------------------------------------
// helpers
// ---------------------------------------------------------------------------
__device__ __forceinline__ uint32_t smem_u32(const void* p) {
    uint32_t a;
    asm("{ .reg .u64 t; cvta.to.shared.u64 t, %1; cvt.u32.u64 %0, t; }" : "=r"(a) : "l"(p));
    return a;
}

__device__ __forceinline__ void ldmatrix_x4(uint32_t* r, uint32_t addr) {
    asm volatile("ldmatrix.sync.aligned.m8n8.x4.shared.b16 {%0,%1,%2,%3}, [%4];"
                 : "=r"(r[0]), "=r"(r[1]), "=r"(r[2]), "=r"(r[3]) : "r"(addr));
}

__device__ __forceinline__ void ldmatrix_x4_trans(uint32_t* r, uint32_t addr) {
    asm volatile("ldmatrix.sync.aligned.m8n8.x4.trans.shared.b16 {%0,%1,%2,%3}, [%4];"
                 : "=r"(r[0]), "=r"(r[1]), "=r"(r[2]), "=r"(r[3]) : "r"(addr));
}

__device__ __forceinline__ void mma_bf16(float* c, const uint32_t* a, const uint32_t* b) {
    asm volatile(
        "mma.sync.aligned.m16n8k16.row.col.f32.bf16.bf16.f32 "
        "{%0,%1,%2,%3}, {%4,%5,%6,%7}, {%8,%9}, {%0,%1,%2,%3};"
        : "+f"(c[0]), "+f"(c[1]), "+f"(c[2]), "+f"(c[3])
        : "r"(a[0]), "r"(a[1]), "r"(a[2]), "r"(a[3]), "r"(b[0]), "r"(b[1]));
}

__device__ __forceinline__ uint32_t pack_bf16(float lo, float hi) {
    __nv_bfloat162 t = __float22bfloat162_rn(make_float2(lo, hi));
    return *(uint32_t*)&t;
}

__device__ __forceinline__ void cp16(uint32_t dst, const void* src) {
    asm volatile("cp.async.cg.shared.global [%0], [%1], 16;" :: "r"(dst), "l"(src));
}
#define CP_COMMIT() asm volatile("cp.async.commit_group;" ::: "memory")
#define CP_WAIT1()  asm volatile("cp.async.wait_group 1;" ::: "memory")
#define CP_WAIT0()  asm volatile("cp.async.wait_group 0;" ::: "memory")

// ---------------------------------------------------------------------------
// fp32 -> bf16 hi/lo split (elementwise)
// ---------------------------------------------------------------------------
__global__ void cvt_hilo(const float4* __restrict__ in,
                         uint2* __restrict__ hi, uint2* __restrict__ lo, int n4)
{
    int i = blockIdx.x * blockDim.x + threadIdx.x;
    if (i >= n4) return;
    float4 f = in[i];
    float v[4] = {f.x, f.y, f.z, f.w};
    float h[4], l[4];
#pragma unroll
    for (int j = 0; j < 4; j++) {
        h[j] = __bfloat162float(__float2bfloat16(v[j]));
        l[j] = v[j] - h[j];
    }
    hi[i] = make_uint2(pack_bf16(h[0], h[1]), pack_bf16(h[2], h[3]));
    lo[i] = make_uint2(pack_bf16(l[0], l[1]), pack_bf16(l[2], l[3]));
}

// ---------------------------------------------------------------------------
// Tensor-core GEMM, bf16x3 compensated, bf16 hi/lo inputs via cp.async.
// C[m,n] = sum_k A[m,k]*B[n,k] + bias[n]
// Block tile 128x128, BK=32, 2-stage double buffer, 256 threads.
// OUTBF=0: fp32 C. OUTBF=1: bf16 hi/lo C.
// smem: 2 stages x [Ah|Al|Bh|Bl] x (128 rows x 80B) = 81920 bytes.
// ---------------------------------------------------------------------------
#define GTILE 10240
#define GSTG  (4 * GTILE)
#define GEMM_SMEM (2 * GSTG)

template <int OUTBF>
__global__ __launch_bounds__(256, 2)
void gemm_bf3(int M, int N, int K,
              const bf16* __restrict__ Ah, const bf16* __restrict__ Al,
              const bf16* __restrict__ Bh, const bf16* __restrict__ Bl,
              const float* __restrict__ bias,
              float* __restrict__ C, bf16* __restrict__ Ch, bf16* __restrict__ Cl)
{
    extern __shared__ char smem[];
    const uint32_t sb = smem_u32(smem);
    const int tid = threadIdx.x, wid = tid >> 5, lane = tid & 31;
    const int bx = blockIdx.x, by = blockIdx.y;
    const int warpM = wid & 1, warpN = wid >> 1;

    // cp.async mapping: thread -> row r, two 16B chunks starting at chunk cb
    const int r = tid >> 1;
    const int cb = (tid & 1) * 2;
    const size_t arow = (size_t)(by * 128 + r) * K;
    const size_t brow = (size_t)(bx * 128 + r) * K;
    const bf16* pAh = Ah + arow;
    const bf16* pAl = Al + arow;
    const bf16* pBh = Bh + brow;
    const bf16* pBl = Bl + brow;
    const uint32_t sdst = sb + (uint32_t)(r * 80 + cb * 16);

    float acc[4][4][4];
#pragma unroll
    for (int i = 0; i < 4; i++)
#pragma unroll
        for (int j = 0; j < 4; j++)
#pragma unroll
            for (int v = 0; v < 4; v++) acc[i][j][v] = 0.f;

    const int KC = K >> 5;

    // stage issue
    auto issue = [&](int kt, int s) {
        const int k0 = kt * 32 + cb * 8;
        const uint32_t d = sdst + (uint32_t)(s * GSTG);
        cp16(d,                 pAh + k0);
        cp16(d + 16,            pAh + k0 + 8);
        cp16(d + GTILE,         pAl + k0);
        cp16(d + GTILE + 16,    pAl + k0 + 8);
        cp16(d + 2 * GTILE,     pBh + k0);
        cp16(d + 2 * GTILE + 16, pBh + k0 + 8);
        cp16(d + 3 * GTILE,     pBl + k0);
        cp16(d + 3 * GTILE + 16, pBl + k0 + 8);
        CP_COMMIT();
    };

    issue(0, 0);

    const int aRow = warpM * 64 + ((lane >> 3) & 1) * 8 + (lane & 7);
    const int aColHalf = (lane >> 4) * 16;
    const int bRow = warpN * 32 + (lane >> 4) * 8 + (lane & 7);
    const int bColHalf = ((lane >> 3) & 1) * 16;

    for (int kt = 0; kt < KC; kt++) {
        if (kt + 1 < KC) issue(kt + 1, (kt + 1) & 1);
        else             CP_COMMIT();       // empty group keeps wait count valid
        CP_WAIT1();
        __syncthreads();

        const uint32_t sAh = sb + (uint32_t)((kt & 1) * GSTG);
        const uint32_t sAl = sAh + GTILE;
        const uint32_t sBh = sAh + 2 * GTILE;
        const uint32_t sBl = sAh + 3 * GTILE;

#pragma unroll
        for (int ks = 0; ks < 2; ks++) {
            uint32_t ah[4][4], al[4][4], bh[4][2], bl[4][2];
            const uint32_t acol = (uint32_t)(ks * 32 + aColHalf);
            const uint32_t bcol = (uint32_t)(ks * 32 + bColHalf);
#pragma unroll
            for (int mt = 0; mt < 4; mt++) {
                uint32_t off = (uint32_t)((aRow + mt * 16) * 80) + acol;
                ldmatrix_x4(ah[mt], sAh + off);
                ldmatrix_x4(al[mt], sAl + off);
            }
#pragma unroll
            for (int pr = 0; pr < 2; pr++) {
                uint32_t off = (uint32_t)((bRow + pr * 16) * 80) + bcol;
                uint32_t r0[4], r1[4];
                ldmatrix_x4(r0, sBh + off);
                ldmatrix_x4(r1, sBl + off);
                bh[pr * 2 + 0][0] = r0[0]; bh[pr * 2 + 0][1] = r0[1];
                bh[pr * 2 + 1][0] = r0[2]; bh[pr * 2 + 1][1] = r0[3];
                bl[pr * 2 + 0][0] = r1[0]; bl[pr * 2 + 0][1] = r1[1];
                bl[pr * 2 + 1][0] = r1[2]; bl[pr * 2 + 1][1] = r1[3];
            }
#pragma unroll
            for (int mt = 0; mt < 4; mt++)
#pragma unroll
                for (int nt = 0; nt < 4; nt++) {
                    mma_bf16(acc[mt][nt], ah[mt], bh[nt]);
                    mma_bf16(acc[mt][nt], ah[mt], bl[nt]);
                    mma_bf16(acc[mt][nt], al[mt], bh[nt]);
                }
        }
        __syncthreads();
    }

    // epilogue
    const int crow = by * 128 + warpM * 64 + (lane >> 2);
    const int ccol = bx * 128 + warpN * 32 + (lane & 3) * 2;
#pragma unroll
    for (int nt = 0; nt < 4; nt++) {
        const int col = ccol + nt * 8;
        const float b0 = bias[col], b1 = bias[col + 1];
#pragma unroll
        for (int mt = 0; mt < 4; mt++) {
            const int r0 = crow + mt * 16;
            const float v00 = acc[mt][nt][0] + b0, v01 = acc[mt][nt][1] + b1;
            const float v10 = acc[mt][nt][2] + b0, v11 = acc[mt][nt][3] + b1;
            if (OUTBF) {
                float h00 = __bfloat162float(__float2bfloat16(v00));
                float h01 = __bfloat162float(__float2bfloat16(v01));
                float h10 = __bfloat162float(__float2bfloat16(v10));
                float h11 = __bfloat162float(__float2bfloat16(v11));
                *(uint32_t*)(Ch + (size_t)r0 * N + col)       = pack_bf16(h00, h01);
                *(uint32_t*)(Cl + (size_t)r0 * N + col)       = pack_bf16(v00 - h00, v01 - h01);
                *(uint32_t*)(Ch + (size_t)(r0 + 8) * N + col) = pack_bf16(h10, h11);
                *(uint32_t*)(Cl + (size_t)(r0 + 8) * N + col) = pack_bf16(v10 - h10, v11 - h11);
            } else {
                *(float2*)(C + (size_t)r0 * N + col)       = make_float2(v00, v01);
                *(float2*)(C + (size_t)(r0 + 8) * N + col) = make_float2(v10, v11);
            }
        }
    }
}

// ---------------------------------------------------------------------------
// Flash attention, mma.sync bf16x3, causal. Inputs/outputs: bf16 hi/lo.
// Grid: (SEQ/128, B*H), 256 threads. 3-stage cp.async K/V pipeline.
// Stage layout (36864B): [Kh 9216 | Kl 9216 | Vh 9216 | Vl 9216], rows 144B.
// ---------------------------------------------------------------------------
#define ASTR 144
#define KV_T 9216
#define STG_A 36864
#define ATT_SMEM (3 * STG_A)       // 110592

__global__ __launch_bounds__(256, 1)
void attn_mma(const bf16* __restrict__ qkvh, const bf16* __restrict__ qkvl,
              bf16* __restrict__ oh, bf16* __restrict__ ol,
              const int* __restrict__ maskp)
{
    extern __shared__ char sm[];
    const uint32_t sb = smem_u32(sm);
    const int tid = threadIdx.x, wid = tid >> 5, lane = tid & 31;
    const int qt = gridDim.x - 1 - blockIdx.x;     // long CTAs first
    const int bh = blockIdx.y;
    const int b = bh >> 4, h = bh & 15;
    const int mask = maskp[0];
    const int q0 = qt * 128;

    // ---- stage Q via cp.async, consume into registers ----
    {
        const int r = tid >> 1, c0 = (tid & 1) * 4;
        const size_t grow = ((size_t)(b * SEQ + q0 + r)) * (3 * DIM) + h * 64 + c0 * 8;
        const uint32_t dh = sb + (uint32_t)(r * ASTR + c0 * 16);
#pragma unroll
        for (int j = 0; j < 4; j++) {
            cp16(dh + j * 16,         qkvh + grow + j * 8);
            cp16(dh + 18432 + j * 16, qkvl + grow + j * 8);
        }
        CP_COMMIT();
        CP_WAIT0();
        __syncthreads();
    }

    uint32_t qh[4][4], ql[4][4];
#pragma unroll
    for (int j = 0; j < 4; j++) {
        uint32_t addr = sb + (uint32_t)((wid * 16 + (lane & 15)) * ASTR
                       + (j * 16 + ((lane >> 4) & 1) * 8) * 2);
        ldmatrix_x4(qh[j], addr);
        ldmatrix_x4(ql[j], addr + 18432);
    }
    __syncthreads();

    float o[8][4];
#pragma unroll
    for (int t = 0; t < 8; t++)
#pragma unroll
        for (int v = 0; v < 4; v++) o[t][v] = 0.f;
    float m0 = -1e30f, m1 = -1e30f, l0 = 0.f, l1 = 0.f;

    const int nkt_load = mask ? (2 * qt + 2) : (SEQ / 64);
    const int nkt_w    = mask ? (2 * qt + 1 + (wid >= 4 ? 1 : 0)) : (SEQ / 64);

    // K/V issue: threads 0-127 -> K, 128-255 -> V
    const int tt = tid & 127;
    const int kr = tt >> 1, kc0 = (tt & 1) * 4;
    const size_t kvcol = h * 64 + (tid < 128 ? DIM : 2 * DIM) + kc0 * 8;
    const uint32_t kvdst = (uint32_t)((tid < 128 ? 0 : 2 * KV_T) + kr * ASTR + kc0 * 16);
    auto issueKV = [&](int kt, int s) {
        const size_t grow = ((size_t)(b * SEQ + kt * 64 + kr)) * (3 * DIM) + kvcol;
        const uint32_t d = sb + (uint32_t)(s * STG_A) + kvdst;
#pragma unroll
        for (int j = 0; j < 4; j++) {
            cp16(d + j * 16,        qkvh + grow + j * 8);
            cp16(d + KV_T + j * 16, qkvl + grow + j * 8);
        }
        CP_COMMIT();
    };

    issueKV(0, 0);
    if (nkt_load > 1) issueKV(1, 1); else CP_COMMIT();

    // fragment addressing (constant part)
    const uint32_t koff = (uint32_t)(
        (((lane >> 4) << 3) + (lane & 7)) * ASTR + (((lane >> 3) & 1) * 8) * 2);
    const uint32_t voff = (uint32_t)(2 * KV_T +
        ((((lane >> 3) & 1) * 8 + (lane & 7)) * ASTR) + (((lane >> 4) & 1) * 8) * 2);

    for (int kt = 0; kt < nkt_load; kt++) {
        CP_WAIT1();
        __syncthreads();
        if (kt + 2 < nkt_load) issueKV(kt + 2, (kt + 2) % 3);
        else                   CP_COMMIT();
        if (kt >= nkt_w) continue;

        const uint32_t stg = sb + (uint32_t)((kt % 3) * STG_A);
        const uint32_t kfrag = stg + koff;
        const uint32_t vfrag = stg + voff;

        // ---- scores = (Q K^T) * 0.125 (bf16x3) ----
        float sc[8][4];
#pragma unroll
        for (int t = 0; t < 8; t++)
#pragma unroll
            for (int v = 0; v < 4; v++) sc[t][v] = 0.f;

#pragma unroll
        for (int j = 0; j < 4; j++) {
#pragma unroll
            for (int t = 0; t < 4; t++) {
                uint32_t addr = kfrag + (uint32_t)(t * 16 * ASTR + j * 32);
                uint32_t rh[4], rl[4];
                ldmatrix_x4(rh, addr);
                ldmatrix_x4(rl, addr + KV_T);
                mma_bf16(sc[2 * t + 0], qh[j], rh);
                mma_bf16(sc[2 * t + 1], qh[j], rh + 2);
                mma_bf16(sc[2 * t + 0], qh[j], rl);
                mma_bf16(sc[2 * t + 1], qh[j], rl + 2);
                mma_bf16(sc[2 * t + 0], ql[j], rh);
                mma_bf16(sc[2 * t + 1], ql[j], rh + 2);
            }
        }
#pragma unroll
        for (int t = 0; t < 8; t++)
#pragma unroll
            for (int v = 0; v < 4; v++) sc[t][v] *= 0.125f;

        // ---- online softmax ----
        const int row0 = q0 + wid * 16 + (lane >> 2);
        const int row1 = row0 + 8;
        const int cbase = kt * 64 + (lane & 3) * 2;
        const bool needmask = mask && (kt * 64 + 63 > q0 + wid * 16);
        if (needmask) {
#pragma unroll
            for (int t = 0; t < 8; t++) {
                int c0 = cbase + t * 8, c1 = c0 + 1;
                if (c0 > row0) sc[t][0] = -1e30f;
                if (c1 > row0) sc[t][1] = -1e30f;
                if (c0 > row1) sc[t][2] = -1e30f;
                if (c1 > row1) sc[t][3] = -1e30f;
            }
        }
        float mt0 = -1e30f, mt1 = -1e30f;
#pragma unroll
        for (int t = 0; t < 8; t++) {
            mt0 = fmaxf(mt0, fmaxf(sc[t][0], sc[t][1]));
            mt1 = fmaxf(mt1, fmaxf(sc[t][2], sc[t][3]));
        }
        mt0 = fmaxf(mt0, __shfl_xor_sync(0xffffffffu, mt0, 1));
        mt0 = fmaxf(mt0, __shfl_xor_sync(0xffffffffu, mt0, 2));
        mt1 = fmaxf(mt1, __shfl_xor_sync(0xffffffffu, mt1, 1));
        mt1 = fmaxf(mt1, __shfl_xor_sync(0xffffffffu, mt1, 2));
        const float mn0 = fmaxf(m0, mt0), mn1 = fmaxf(m1, mt1);
        const float a0 = __expf(m0 - mn0), a1 = __expf(m1 - mn1);

        uint32_t ph[8][2], pl[8][2];
        float s0 = 0.f, s1 = 0.f;
#pragma unroll
        for (int t = 0; t < 8; t++) {
            float p00 = __expf(sc[t][0] - mn0);
            float p01 = __expf(sc[t][1] - mn0);
            float p10 = __expf(sc[t][2] - mn1);
            float p11 = __expf(sc[t][3] - mn1);
            s0 += p00 + p01;
            s1 += p10 + p11;
            ph[t][0] = pack_bf16(p00, p01);
            ph[t][1] = pack_bf16(p10, p11);
            float h00 = __bfloat162float(__float2bfloat16(p00));
            float h01 = __bfloat162float(__float2bfloat16(p01));
            float h10 = __bfloat162float(__float2bfloat16(p10));
            float h11 = __bfloat162float(__float2bfloat16(p11));
            pl[t][0] = pack_bf16(p00 - h00, p01 - h01);
            pl[t][1] = pack_bf16(p10 - h10, p11 - h11);
        }
        s0 += __shfl_xor_sync(0xffffffffu, s0, 1);
        s0 += __shfl_xor_sync(0xffffffffu, s0, 2);
        s1 += __shfl_xor_sync(0xffffffffu, s1, 1);
        s1 += __shfl_xor_sync(0xffffffffu, s1, 2);
        m0 = mn0; m1 = mn1;
        l0 = l0 * a0 + s0;
        l1 = l1 * a1 + s1;
#pragma unroll
        for (int t = 0; t < 8; t++) {
            o[t][0] *= a0; o[t][1] *= a0;
            o[t][2] *= a1; o[t][3] *= a1;
        }

        // ---- O += P V (bf16x3) ----
#pragma unroll
        for (int j = 0; j < 4; j++) {
            uint32_t afh[4] = { ph[2*j][0], ph[2*j][1], ph[2*j+1][0], ph[2*j+1][1] };
            uint32_t afl[4] = { pl[2*j][0], pl[2*j][1], pl[2*j+1][0], pl[2*j+1][1] };
#pragma unroll
            for (int t = 0; t < 4; t++) {
                uint32_t addr = vfrag + (uint32_t)(j * 16 * ASTR + t * 32);
                uint32_t rh[4], rl[4];
                ldmatrix_x4_trans(rh, addr);
                ldmatrix_x4_trans(rl, addr + KV_T);
                mma_bf16(o[2 * t + 0], afh, rh);
                mma_bf16(o[2 * t + 1], afh, rh + 2);
                mma_bf16(o[2 * t + 0], afh, rl);
                mma_bf16(o[2 * t + 1], afh, rl + 2);
                mma_bf16(o[2 * t + 0], afl, rh);
                mma_bf16(o[2 * t + 1], afl, rh + 2);
            }
        }
    }

    // ---- write O as bf16 hi/lo ----
    const float il0 = 1.0f / l0, il1 = 1.0f / l1;
    const int orow = q0 + wid * 16 + (lane >> 2);
    const size_t obase = ((size_t)b * SEQ + orow) * DIM + h * 64 + (lane & 3) * 2;
#pragma unroll
    for (int t = 0; t < 8; t++) {
        float v00 = o[t][0] * il0, v01 = o[t][1] * il0;
        float v10 = o[t][2] * il1, v11 = o[t][3] * il1;
        float h00 = __bfloat162float(__float2bfloat16(v00));
        float h01 = __bfloat162float(__float2bfloat16(v01));
        float h10 = __bfloat162float(__float2bfloat16(v10));
        float h11 = __bfloat162float(__float2bfloat16(v11));
        *(uint32_t*)(oh + obase + t * 8)           = pack_bf16(h00, h01);
        *(uint32_t*)(ol + obase + t * 8)           = pack_bf16(v00 - h00, v01 - h01);
        *(uint32_t*)(oh + obase + 8 * DIM + t * 8) = pack_bf16(h10, h11);
        *(uint32_t*)(ol + obase + 8 * DIM + t * 8) = pack_bf16(v10 - h10, v11 - h11);
    }
}

// ---------------------------------------------------------------------------
// Launch
// ---------------------------------------------------------------------------
extern "C" void kernel_launch(void* const* d_in, const int* in_sizes, int n_in,
                              void* d_out, int out_size)
{
    const float* x     = (const float*)d_in[0];
    const float* w_in  = (const float*)d_in[1];
    const float* b_in  = (const float*)d_in[2];
    const float* w_out = (const float*)d_in[3];
    const float* b_out = (const float*)d_in[4];
    const int*   mask  = (const int*)d_in[5];
    float* out = (float*)d_out;

    bf16 *xh, *xl, *wih, *wil, *woh, *wol, *qkvh, *qkvl, *ah, *al;
    cudaGetSymbolAddress((void**)&xh,  g_xh);
    cudaGetSymbolAddress((void**)&xl,  g_xl);
    cudaGetSymbolAddress((void**)&wih, g_wih);
    cudaGetSymbolAddress((void**)&wil, g_wil);
    cudaGetSymbolAddress((void**)&woh, g_woh);
    cudaGetSymbolAddress((void**)&wol, g_wol);
    cudaGetSymbolAddress((void**)&qkvh, g_qkvh);
    cudaGetSymbolAddress((void**)&qkvl, g_qkvl);
    cudaGetSymbolAddress((void**)&ah,  g_ah);
    cudaGetSymbolAddress((void**)&al,  g_al);

    const int M = BATCH * SEQ;      // 4096
    const int K = DIM;              // 1024
    const int N1 = 3 * DIM;         // 3072
    const int N2 = DIM;             // 1024

    cudaFuncSetAttribute(gemm_bf3<0>, cudaFuncAttributeMaxDynamicSharedMemorySize, GEMM_SMEM);
    cudaFuncSetAttribute(gemm_bf3<1>, cudaFuncAttributeMaxDynamicSharedMemorySize, GEMM_SMEM);
    cudaFuncSetAttribute(attn_mma, cudaFuncAttributeMaxDynamicSharedMemorySize, ATT_SMEM);

    // 0) convert inputs to bf16 hi/lo
    {
        int n4x = M * K / 4;          // 1048576
        int n4w = N1 * K / 4;         // 786432
        int n4o = N2 * K / 4;         // 262144
        cvt_hilo<<<(n4x + 255) / 256, 256>>>((const float4*)x, (uint2*)xh, (uint2*)xl, n4x);
        cvt_hilo<<<(n4w + 255) / 256, 256>>>((const float4*)w_in, (uint2*)wih, (uint2*)wil, n4w);
        cvt_hilo<<<(n4o + 255) / 256, 256>>>((const float4*)w_out, (uint2*)woh, (uint2*)wol, n4o);
    }
    // 1) QKV projection -> bf16 hi/lo qkv
    {
        dim3 grid(N1 / 128, M / 128);
        gemm_bf3<1><<<grid, 256, GEMM_SMEM>>>(M, N1, K, xh, xl, wih, wil, b_in,
                                              nullptr, qkvh, qkvl);
    }
    // 2) causal attention -> bf16 hi/lo
    {
        dim3 grid(SEQ / 128, BATCH * HEADS);
        attn_mma<<<grid, 256, ATT_SMEM>>>(qkvh, qkvl, ah, al, mask);
    }
    // 3) output projection -> fp32 out
    {
        dim3 grid(N2 / 128, M / 128);
        gemm_bf3<0><<<grid, 256, GEMM_SMEM>>>(M, N2, K, ah, al, woh, wol, b_out,
                                              out, nullptr, nullptr);
    }
}

// round 7
// speedup vs baseline: 4.4723x; 1.3247x over previous
#include <cuda_runtime.h>
#include <cuda_fp16.h>
#include <cstdint>

// Problem constants
#define BATCH 2
#define SEQ   2048
#define DIM   1024
#define HEADS 16
#define DHEAD 64

// Scratch (device globals — no allocations allowed)
__device__ __half g_xh [(size_t)BATCH * SEQ * DIM];
__device__ __half g_wih[(size_t)3 * DIM * DIM];
__device__ __half g_wil[(size_t)3 * DIM * DIM];
__device__ __half g_woh[(size_t)DIM * DIM];
__device__ __half g_wol[(size_t)DIM * DIM];
__device__ __half g_qkvh[(size_t)BATCH * SEQ * 3 * DIM];
__device__ __half g_qkvl[(size_t)BATCH * SEQ * 3 * DIM];
__device__ __half g_ah [(size_t)BATCH * SEQ * DIM];

typedef __half f16;

// ---------------------------------------------------------------------------
// helpers
// ---------------------------------------------------------------------------
__device__ __forceinline__ uint32_t smem_u32(const void* p) {
    uint32_t a;
    asm("{ .reg .u64 t; cvta.to.shared.u64 t, %1; cvt.u32.u64 %0, t; }" : "=r"(a) : "l"(p));
    return a;
}

__device__ __forceinline__ void ldmatrix_x4(uint32_t* r, uint32_t addr) {
    asm volatile("ldmatrix.sync.aligned.m8n8.x4.shared.b16 {%0,%1,%2,%3}, [%4];"
                 : "=r"(r[0]), "=r"(r[1]), "=r"(r[2]), "=r"(r[3]) : "r"(addr));
}

__device__ __forceinline__ void ldmatrix_x4_trans(uint32_t* r, uint32_t addr) {
    asm volatile("ldmatrix.sync.aligned.m8n8.x4.trans.shared.b16 {%0,%1,%2,%3}, [%4];"
                 : "=r"(r[0]), "=r"(r[1]), "=r"(r[2]), "=r"(r[3]) : "r"(addr));
}

__device__ __forceinline__ void mma_f16(float* c, const uint32_t* a, const uint32_t* b) {
    asm volatile(
        "mma.sync.aligned.m16n8k16.row.col.f32.f16.f16.f32 "
        "{%0,%1,%2,%3}, {%4,%5,%6,%7}, {%8,%9}, {%0,%1,%2,%3};"
        : "+f"(c[0]), "+f"(c[1]), "+f"(c[2]), "+f"(c[3])
        : "r"(a[0]), "r"(a[1]), "r"(a[2]), "r"(a[3]), "r"(b[0]), "r"(b[1]));
}

__device__ __forceinline__ uint32_t pack_f16(float a, float b) {
    __half2 t = __floats2half2_rn(a, b);
    return *(uint32_t*)&t;
}

__device__ __forceinline__ void cp16(uint32_t dst, const void* src) {
    asm volatile("cp.async.cg.shared.global [%0], [%1], 16;" :: "r"(dst), "l"(src));
}
#define CP_COMMIT() asm volatile("cp.async.commit_group;" ::: "memory")
#define CP_WAIT1()  asm volatile("cp.async.wait_group 1;" ::: "memory")
#define CP_WAIT0()  asm volatile("cp.async.wait_group 0;" ::: "memory")

// ---------------------------------------------------------------------------
// fp32 -> fp16 converters
// ---------------------------------------------------------------------------
__global__ void cvt_hi(const float4* __restrict__ in, uint2* __restrict__ hi, int n4)
{
    int i = blockIdx.x * blockDim.x + threadIdx.x;
    if (i >= n4) return;
    float4 f = in[i];
    hi[i] = make_uint2(pack_f16(f.x, f.y), pack_f16(f.z, f.w));
}

__global__ void cvt_hilo(const float4* __restrict__ in,
                         uint2* __restrict__ hi, uint2* __restrict__ lo, int n4)
{
    int i = blockIdx.x * blockDim.x + threadIdx.x;
    if (i >= n4) return;
    float4 f = in[i];
    float v[4] = {f.x, f.y, f.z, f.w};
    float h[4];
#pragma unroll
    for (int j = 0; j < 4; j++) h[j] = __half2float(__float2half_rn(v[j]));
    hi[i] = make_uint2(pack_f16(h[0], h[1]), pack_f16(h[2], h[3]));
    lo[i] = make_uint2(pack_f16(v[0] - h[0], v[1] - h[1]),
                       pack_f16(v[2] - h[2], v[3] - h[3]));
}

// ---------------------------------------------------------------------------
// Tensor-core GEMM, fp16x2 compensated: C = Ah*(Bh+Bl) + bias
// Block tile 128x128, BK=32, 3-stage cp.async, 256 threads, 2 CTAs/SM.
// Stage = [Ah | Bh | Bl], rows padded to 80 B. 3 stages = 92160 B.
// ---------------------------------------------------------------------------
#define GTILE 10240
#define GSTG  (3 * GTILE)
#define GEMM_SMEM (3 * GSTG)

template <int OUTBF>
__global__ __launch_bounds__(256, 2)
void gemm_f16x2(int M, int N, int K,
                const f16* __restrict__ Ah,
                const f16* __restrict__ Bh, const f16* __restrict__ Bl,
                const float* __restrict__ bias,
                float* __restrict__ C, f16* __restrict__ Ch, f16* __restrict__ Cl)
{
    extern __shared__ char smem[];
    const uint32_t sb = smem_u32(smem);
    const int tid = threadIdx.x, wid = tid >> 5, lane = tid & 31;
    const int bx = blockIdx.x, by = blockIdx.y;
    const int warpM = wid & 1, warpN = wid >> 1;

    const int r = tid >> 1;
    const int cb = (tid & 1) * 2;
    const f16* pAh = Ah + (size_t)(by * 128 + r) * K;
    const f16* pBh = Bh + (size_t)(bx * 128 + r) * K;
    const f16* pBl = Bl + (size_t)(bx * 128 + r) * K;
    const uint32_t sdst = sb + (uint32_t)(r * 80 + cb * 16);

    float acc[4][4][4];
#pragma unroll
    for (int i = 0; i < 4; i++)
#pragma unroll
        for (int j = 0; j < 4; j++)
#pragma unroll
            for (int v = 0; v < 4; v++) acc[i][j][v] = 0.f;

    const int KC = K >> 5;

    auto issue = [&](int kt, int s) {
        const int k0 = kt * 32 + cb * 8;
        const uint32_t d = sdst + (uint32_t)(s * GSTG);
        cp16(d,                  pAh + k0);
        cp16(d + 16,             pAh + k0 + 8);
        cp16(d + GTILE,          pBh + k0);
        cp16(d + GTILE + 16,     pBh + k0 + 8);
        cp16(d + 2 * GTILE,      pBl + k0);
        cp16(d + 2 * GTILE + 16, pBl + k0 + 8);
        CP_COMMIT();
    };

    issue(0, 0);
    issue(1, 1);

    const int aRow = warpM * 64 + ((lane >> 3) & 1) * 8 + (lane & 7);
    const int aColHalf = (lane >> 4) * 16;
    const int bRow = warpN * 32 + (lane >> 4) * 8 + (lane & 7);
    const int bColHalf = ((lane >> 3) & 1) * 16;

    for (int kt = 0; kt < KC; kt++) {
        CP_WAIT1();
        __syncthreads();
        if (kt + 2 < KC) issue(kt + 2, (kt + 2) % 3);
        else             CP_COMMIT();

        const uint32_t sAh = sb + (uint32_t)((kt % 3) * GSTG);
        const uint32_t sBh = sAh + GTILE;
        const uint32_t sBl = sAh + 2 * GTILE;

#pragma unroll
        for (int ks = 0; ks < 2; ks++) {
            uint32_t ah[4][4], bh[4][2], bl[4][2];
            const uint32_t acol = (uint32_t)(ks * 32 + aColHalf);
            const uint32_t bcol = (uint32_t)(ks * 32 + bColHalf);
#pragma unroll
            for (int mt = 0; mt < 4; mt++) {
                uint32_t off = (uint32_t)((aRow + mt * 16) * 80) + acol;
                ldmatrix_x4(ah[mt], sAh + off);
            }
#pragma unroll
            for (int pr = 0; pr < 2; pr++) {
                uint32_t off = (uint32_t)((bRow + pr * 16) * 80) + bcol;
                uint32_t r0[4], r1[4];
                ldmatrix_x4(r0, sBh + off);
                ldmatrix_x4(r1, sBl + off);
                bh[pr * 2 + 0][0] = r0[0]; bh[pr * 2 + 0][1] = r0[1];
                bh[pr * 2 + 1][0] = r0[2]; bh[pr * 2 + 1][1] = r0[3];
                bl[pr * 2 + 0][0] = r1[0]; bl[pr * 2 + 0][1] = r1[1];
                bl[pr * 2 + 1][0] = r1[2]; bl[pr * 2 + 1][1] = r1[3];
            }
#pragma unroll
            for (int mt = 0; mt < 4; mt++)
#pragma unroll
                for (int nt = 0; nt < 4; nt++) {
                    mma_f16(acc[mt][nt], ah[mt], bh[nt]);
                    mma_f16(acc[mt][nt], ah[mt], bl[nt]);
                }
        }
        __syncthreads();
    }

    const int crow = by * 128 + warpM * 64 + (lane >> 2);
    const int ccol = bx * 128 + warpN * 32 + (lane & 3) * 2;
#pragma unroll
    for (int nt = 0; nt < 4; nt++) {
        const int col = ccol + nt * 8;
        const float b0 = bias[col], b1 = bias[col + 1];
#pragma unroll
        for (int mt = 0; mt < 4; mt++) {
            const int r0 = crow + mt * 16;
            const float v00 = acc[mt][nt][0] + b0, v01 = acc[mt][nt][1] + b1;
            const float v10 = acc[mt][nt][2] + b0, v11 = acc[mt][nt][3] + b1;
            if (OUTBF) {
                float h00 = __half2float(__float2half_rn(v00));
                float h01 = __half2float(__float2half_rn(v01));
                float h10 = __half2float(__float2half_rn(v10));
                float h11 = __half2float(__float2half_rn(v11));
                *(uint32_t*)(Ch + (size_t)r0 * N + col)       = pack_f16(h00, h01);
                *(uint32_t*)(Cl + (size_t)r0 * N + col)       = pack_f16(v00 - h00, v01 - h01);
                *(uint32_t*)(Ch + (size_t)(r0 + 8) * N + col) = pack_f16(h10, h11);
                *(uint32_t*)(Cl + (size_t)(r0 + 8) * N + col) = pack_f16(v10 - h10, v11 - h11);
            } else {
                *(float2*)(C + (size_t)r0 * N + col)       = make_float2(v00, v01);
                *(float2*)(C + (size_t)(r0 + 8) * N + col) = make_float2(v10, v11);
            }
        }
    }
}

// ---------------------------------------------------------------------------
// Flash attention, mma.sync fp16x2, causal.
// S = Qh*(Kh+Kl); O = Ph*(Vh+Vl). Grid: (SEQ/128, B*H), 256 threads.
// 3-stage cp.async K/V pipeline; stage [Kh|Kl|Vh|Vl], rows 144 B.
// ---------------------------------------------------------------------------
#define ASTR 144
#define KV_T 9216
#define STG_A 36864
#define ATT_SMEM (3 * STG_A)       // 110592

__global__ __launch_bounds__(256, 1)
void attn_mma(const f16* __restrict__ qkvh, const f16* __restrict__ qkvl,
              f16* __restrict__ oh, const int* __restrict__ maskp)
{
    extern __shared__ char sm[];
    const uint32_t sb = smem_u32(sm);
    const int tid = threadIdx.x, wid = tid >> 5, lane = tid & 31;
    const int qt = gridDim.x - 1 - blockIdx.x;     // long CTAs first
    const int bh = blockIdx.y;
    const int b = bh >> 4, h = bh & 15;
    const int mask = maskp[0];
    const int q0 = qt * 128;

    // ---- stage Qh via cp.async, consume into registers ----
    {
        const int r = tid >> 1, c0 = (tid & 1) * 4;
        const size_t grow = ((size_t)(b * SEQ + q0 + r)) * (3 * DIM) + h * 64 + c0 * 8;
        const uint32_t dh = sb + (uint32_t)(r * ASTR + c0 * 16);
#pragma unroll
        for (int j = 0; j < 4; j++)
            cp16(dh + j * 16, qkvh + grow + j * 8);
        CP_COMMIT();
        CP_WAIT0();
        __syncthreads();
    }

    uint32_t qh[4][4];
#pragma unroll
    for (int j = 0; j < 4; j++) {
        uint32_t addr = sb + (uint32_t)((wid * 16 + (lane & 15)) * ASTR
                       + (j * 16 + ((lane >> 4) & 1) * 8) * 2);
        ldmatrix_x4(qh[j], addr);
    }
    __syncthreads();

    float o[8][4];
#pragma unroll
    for (int t = 0; t < 8; t++)
#pragma unroll
        for (int v = 0; v < 4; v++) o[t][v] = 0.f;
    float m0 = -1e30f, m1 = -1e30f, l0 = 0.f, l1 = 0.f;

    const int nkt_load = mask ? (2 * qt + 2) : (SEQ / 64);
    const int nkt_w    = mask ? (2 * qt + 1 + (wid >= 4 ? 1 : 0)) : (SEQ / 64);

    // K/V issue: threads 0-127 -> K, 128-255 -> V (hi+lo each)
    const int tt = tid & 127;
    const int kr = tt >> 1, kc0 = (tt & 1) * 4;
    const size_t kvcol = h * 64 + (tid < 128 ? DIM : 2 * DIM) + kc0 * 8;
    const uint32_t kvdst = (uint32_t)((tid < 128 ? 0 : 2 * KV_T) + kr * ASTR + kc0 * 16);
    auto issueKV = [&](int kt, int s) {
        const size_t grow = ((size_t)(b * SEQ + kt * 64 + kr)) * (3 * DIM) + kvcol;
        const uint32_t d = sb + (uint32_t)(s * STG_A) + kvdst;
#pragma unroll
        for (int j = 0; j < 4; j++) {
            cp16(d + j * 16,        qkvh + grow + j * 8);
            cp16(d + KV_T + j * 16, qkvl + grow + j * 8);
        }
        CP_COMMIT();
    };

    issueKV(0, 0);
    if (nkt_load > 1) issueKV(1, 1); else CP_COMMIT();

    const uint32_t koff = (uint32_t)(
        (((lane >> 4) << 3) + (lane & 7)) * ASTR + (((lane >> 3) & 1) * 8) * 2);
    const uint32_t voff = (uint32_t)(2 * KV_T +
        ((((lane >> 3) & 1) * 8 + (lane & 7)) * ASTR) + (((lane >> 4) & 1) * 8) * 2);

    for (int kt = 0; kt < nkt_load; kt++) {
        CP_WAIT1();
        __syncthreads();
        if (kt + 2 < nkt_load) issueKV(kt + 2, (kt + 2) % 3);
        else                   CP_COMMIT();
        if (kt >= nkt_w) continue;

        const uint32_t stg = sb + (uint32_t)((kt % 3) * STG_A);
        const uint32_t kfrag = stg + koff;
        const uint32_t vfrag = stg + voff;

        // ---- scores = Qh*(Kh+Kl), then * 0.125 ----
        float sc[8][4];
#pragma unroll
        for (int t = 0; t < 8; t++)
#pragma unroll
            for (int v = 0; v < 4; v++) sc[t][v] = 0.f;

#pragma unroll
        for (int j = 0; j < 4; j++) {
#pragma unroll
            for (int t = 0; t < 4; t++) {
                uint32_t addr = kfrag + (uint32_t)(t * 16 * ASTR + j * 32);
                uint32_t rh[4], rl[4];
                ldmatrix_x4(rh, addr);
                ldmatrix_x4(rl, addr + KV_T);
                mma_f16(sc[2 * t + 0], qh[j], rh);
                mma_f16(sc[2 * t + 1], qh[j], rh + 2);
                mma_f16(sc[2 * t + 0], qh[j], rl);
                mma_f16(sc[2 * t + 1], qh[j], rl + 2);
            }
        }
#pragma unroll
        for (int t = 0; t < 8; t++)
#pragma unroll
            for (int v = 0; v < 4; v++) sc[t][v] *= 0.125f;

        // ---- online softmax ----
        const int row0 = q0 + wid * 16 + (lane >> 2);
        const int row1 = row0 + 8;
        const int cbase = kt * 64 + (lane & 3) * 2;
        const bool needmask = mask && (kt * 64 + 63 > q0 + wid * 16);
        if (needmask) {
#pragma unroll
            for (int t = 0; t < 8; t++) {
                int c0 = cbase + t * 8, c1 = c0 + 1;
                if (c0 > row0) sc[t][0] = -1e30f;
                if (c1 > row0) sc[t][1] = -1e30f;
                if (c0 > row1) sc[t][2] = -1e30f;
                if (c1 > row1) sc[t][3] = -1e30f;
            }
        }
        float mt0 = -1e30f, mt1 = -1e30f;
#pragma unroll
        for (int t = 0; t < 8; t++) {
            mt0 = fmaxf(mt0, fmaxf(sc[t][0], sc[t][1]));
            mt1 = fmaxf(mt1, fmaxf(sc[t][2], sc[t][3]));
        }
        mt0 = fmaxf(mt0, __shfl_xor_sync(0xffffffffu, mt0, 1));
        mt0 = fmaxf(mt0, __shfl_xor_sync(0xffffffffu, mt0, 2));
        mt1 = fmaxf(mt1, __shfl_xor_sync(0xffffffffu, mt1, 1));
        mt1 = fmaxf(mt1, __shfl_xor_sync(0xffffffffu, mt1, 2));
        const float mn0 = fmaxf(m0, mt0), mn1 = fmaxf(m1, mt1);
        const float a0 = __expf(m0 - mn0), a1 = __expf(m1 - mn1);

        uint32_t ph[8][2];
        float s0 = 0.f, s1 = 0.f;
#pragma unroll
        for (int t = 0; t < 8; t++) {
            float p00 = __expf(sc[t][0] - mn0);
            float p01 = __expf(sc[t][1] - mn0);
            float p10 = __expf(sc[t][2] - mn1);
            float p11 = __expf(sc[t][3] - mn1);
            s0 += p00 + p01;
            s1 += p10 + p11;
            ph[t][0] = pack_f16(p00, p01);
            ph[t][1] = pack_f16(p10, p11);
        }
        s0 += __shfl_xor_sync(0xffffffffu, s0, 1);
        s0 += __shfl_xor_sync(0xffffffffu, s0, 2);
        s1 += __shfl_xor_sync(0xffffffffu, s1, 1);
        s1 += __shfl_xor_sync(0xffffffffu, s1, 2);
        m0 = mn0; m1 = mn1;
        l0 = l0 * a0 + s0;
        l1 = l1 * a1 + s1;
#pragma unroll
        for (int t = 0; t < 8; t++) {
            o[t][0] *= a0; o[t][1] *= a0;
            o[t][2] *= a1; o[t][3] *= a1;
        }

        // ---- O += Ph*(Vh+Vl) ----
#pragma unroll
        for (int j = 0; j < 4; j++) {
            uint32_t afh[4] = { ph[2*j][0], ph[2*j][1], ph[2*j+1][0], ph[2*j+1][1] };
#pragma unroll
            for (int t = 0; t < 4; t++) {
                uint32_t addr = vfrag + (uint32_t)(j * 16 * ASTR + t * 32);
                uint32_t rh[4], rl[4];
                ldmatrix_x4_trans(rh, addr);
                ldmatrix_x4_trans(rl, addr + KV_T);
                mma_f16(o[2 * t + 0], afh, rh);
                mma_f16(o[2 * t + 1], afh, rh + 2);
                mma_f16(o[2 * t + 0], afh, rl);
                mma_f16(o[2 * t + 1], afh, rl + 2);
            }
        }
    }

    // ---- write O (fp16 hi only — feeds proj as A operand) ----
    const float il0 = 1.0f / l0, il1 = 1.0f / l1;
    const int orow = q0 + wid * 16 + (lane >> 2);
    const size_t obase = ((size_t)b * SEQ + orow) * DIM + h * 64 + (lane & 3) * 2;
#pragma unroll
    for (int t = 0; t < 8; t++) {
        *(uint32_t*)(oh + obase + t * 8)           = pack_f16(o[t][0] * il0, o[t][1] * il0);
        *(uint32_t*)(oh + obase + 8 * DIM + t * 8) = pack_f16(o[t][2] * il1, o[t][3] * il1);
    }
}

// ---------------------------------------------------------------------------
// Launch
// ---------------------------------------------------------------------------
extern "C" void kernel_launch(void* const* d_in, const int* in_sizes, int n_in,
                              void* d_out, int out_size)
{
    const float* x     = (const float*)d_in[0];
    const float* w_in  = (const float*)d_in[1];
    const float* b_in  = (const float*)d_in[2];
    const float* w_out = (const float*)d_in[3];
    const float* b_out = (const float*)d_in[4];
    const int*   mask  = (const int*)d_in[5];
    float* out = (float*)d_out;

    f16 *xh, *wih, *wil, *woh, *wol, *qkvh, *qkvl, *ah;
    cudaGetSymbolAddress((void**)&xh,  g_xh);
    cudaGetSymbolAddress((void**)&wih, g_wih);
    cudaGetSymbolAddress((void**)&wil, g_wil);
    cudaGetSymbolAddress((void**)&woh, g_woh);
    cudaGetSymbolAddress((void**)&wol, g_wol);
    cudaGetSymbolAddress((void**)&qkvh, g_qkvh);
    cudaGetSymbolAddress((void**)&qkvl, g_qkvl);
    cudaGetSymbolAddress((void**)&ah,  g_ah);

    const int M = BATCH * SEQ;      // 4096
    const int K = DIM;              // 1024
    const int N1 = 3 * DIM;         // 3072
    const int N2 = DIM;             // 1024

    cudaFuncSetAttribute(gemm_f16x2<0>, cudaFuncAttributeMaxDynamicSharedMemorySize, GEMM_SMEM);
    cudaFuncSetAttribute(gemm_f16x2<1>, cudaFuncAttributeMaxDynamicSharedMemorySize, GEMM_SMEM);
    cudaFuncSetAttribute(attn_mma, cudaFuncAttributeMaxDynamicSharedMemorySize, ATT_SMEM);

    // 0) convert inputs (x: hi only; weights: hi+lo)
    {
        int n4x = M * K / 4;
        int n4w = N1 * K / 4;
        int n4o = N2 * K / 4;
        cvt_hi  <<<(n4x + 255) / 256, 256>>>((const float4*)x, (uint2*)xh, n4x);
        cvt_hilo<<<(n4w + 255) / 256, 256>>>((const float4*)w_in, (uint2*)wih, (uint2*)wil, n4w);
        cvt_hilo<<<(n4o + 255) / 256, 256>>>((const float4*)w_out, (uint2*)woh, (uint2*)wol, n4o);
    }
    // 1) QKV projection -> fp16 hi/lo
    {
        dim3 grid(N1 / 128, M / 128);
        gemm_f16x2<1><<<grid, 256, GEMM_SMEM>>>(M, N1, K, xh, wih, wil, b_in,
                                                nullptr, qkvh, qkvl);
    }
    // 2) causal attention -> fp16 hi
    {
        dim3 grid(SEQ / 128, BATCH * HEADS);
        attn_mma<<<grid, 256, ATT_SMEM>>>(qkvh, qkvl, ah, mask);
    }
    // 3) output projection -> fp32 out
    {
        dim3 grid(N2 / 128, M / 128);
        gemm_f16x2<0><<<grid, 256, GEMM_SMEM>>>(M, N2, K, ah, woh, wol, b_out,
                                                out, nullptr, nullptr);
    }
}